// round 11
// baseline (speedup 1.0000x reference)
#include <cuda_runtime.h>
#include <math_constants.h>

// Coords padded to float4 -> single LDG.128 per gather (16B aligned by definition).
__device__ float4 g_coords4[131072];

__global__ void __launch_bounds__(256) pad_coords_kernel(
    const float* __restrict__ coords, int n)
{
    int i = blockIdx.x * blockDim.x + threadIdx.x;
    if (i < n) {
        g_coords4[i] = make_float4(coords[3 * i + 0],
                                   coords[3 * i + 1],
                                   coords[3 * i + 2], 0.0f);
    }
    __threadfence();
    cudaTriggerProgrammaticLaunchCompletion();
}

#define EPB 512   // edges per block (2 per thread, 256 threads)

// Output layout (float32, out_size = 6*E):
//   [0 , 3E) : vec [E,3]   [3E,4E) : dist   [4E,5E) : switch   [5E,6E) : mask
__global__ void __launch_bounds__(256, 7) graph_edge_kernel(
    const int*   __restrict__ esrc,
    const int*   __restrict__ edst,
    const float* __restrict__ shifts,
    const float* __restrict__ cells,
    float*       __restrict__ out,
    int E)
{
    __shared__ float s_cells[9];
    __shared__ float stage[EPB * 3];   // shifts in -> vec out (slot-owned overwrite)

    const int t = threadIdx.x;
    const int base = blockIdx.x * EPB;
    const int i0 = base + t;
    const int i1 = i0 + 256;
    const bool a0 = (i0 < E);
    const bool a1 = (i1 < E);
    const int nf = (base < E) ? min(EPB, E - base) * 3 : 0;

    if (t < 9) s_cells[t] = __ldg(cells + t);

    // ---- idx loads first: they head the long dependence chain ----
    int s0 = 0, d0 = 0, s1 = 0, d1 = 0;
    if (a0) { s0 = __ldg(esrc + i0); d0 = __ldg(edst + i0); }
    if (a1) { s1 = __ldg(esrc + i1); d1 = __ldg(edst + i1); }

    // ---- stage shifts into smem: 6 coalesced scalar loads (alignment-safe) ----
    #pragma unroll
    for (int k = t; k < EPB * 3; k += 256) {
        if (k < nf) stage[k] = __ldg(shifts + base * 3 + k);
    }

    __syncthreads();   // covers s_cells + shift staging

    // PDL: gathers read pad_coords_kernel's output — wait for it here.
    cudaGridDependencySynchronize();

    float4 cs0 = make_float4(0.f, 0.f, 0.f, 0.f), cd0 = cs0, cs1 = cs0, cd1 = cs0;
    if (a0) { cd0 = g_coords4[d0]; cs0 = g_coords4[s0]; }
    if (a1) { cd1 = g_coords4[d1]; cs1 = g_coords4[s1]; }

    const float c00 = s_cells[0], c01 = s_cells[1], c02 = s_cells[2];
    const float c10 = s_cells[3], c11 = s_cells[4], c12 = s_cells[5];
    const float c20 = s_cells[6], c21 = s_cells[7], c22 = s_cells[8];

    float dist0 = 0.f, sw0 = 0.f, mf0 = 0.f;
    float dist1 = 0.f, sw1 = 0.f, mf1 = 0.f;

    if (a0) {
        // read own shift slots, then overwrite the SAME slots with vec
        const float sx = stage[3 * t + 0];
        const float sy = stage[3 * t + 1];
        const float sz = stage[3 * t + 2];
        const float vx = (cd0.x - cs0.x) + sx * c00 + sy * c10 + sz * c20;
        const float vy = (cd0.y - cs0.y) + sx * c01 + sy * c11 + sz * c21;
        const float vz = (cd0.z - cs0.z) + sx * c02 + sy * c12 + sz * c22;
        stage[3 * t + 0] = vx;
        stage[3 * t + 1] = vy;
        stage[3 * t + 2] = vz;
        dist0 = sqrtf(vx * vx + vy * vy + vz * vz);
        const bool m = dist0 < 5.0f;
        sw0 = m ? (0.5f * __cosf(dist0 * (CUDART_PI_F / 5.0f)) + 0.5f) : 0.0f;
        mf0 = m ? 1.0f : 0.0f;
    }
    if (a1) {
        const int u = t + 256;
        const float sx = stage[3 * u + 0];
        const float sy = stage[3 * u + 1];
        const float sz = stage[3 * u + 2];
        const float vx = (cd1.x - cs1.x) + sx * c00 + sy * c10 + sz * c20;
        const float vy = (cd1.y - cs1.y) + sx * c01 + sy * c11 + sz * c21;
        const float vz = (cd1.z - cs1.z) + sx * c02 + sy * c12 + sz * c22;
        stage[3 * u + 0] = vx;
        stage[3 * u + 1] = vy;
        stage[3 * u + 2] = vz;
        dist1 = sqrtf(vx * vx + vy * vy + vz * vz);
        const bool m = dist1 < 5.0f;
        sw1 = m ? (0.5f * __cosf(dist1 * (CUDART_PI_F / 5.0f)) + 0.5f) : 0.0f;
        mf1 = m ? 1.0f : 0.0f;
    }

    __syncthreads();   // vec staging complete

    // ---- contiguous scalar stores of staged vec ----
    #pragma unroll
    for (int k = t; k < EPB * 3; k += 256) {
        if (k < nf) out[base * 3 + k] = stage[k];
    }

    if (a0) {
        out[3 * E + i0] = dist0;
        out[4 * E + i0] = sw0;
        out[5 * E + i0] = mf0;
    }
    if (a1) {
        out[3 * E + i1] = dist1;
        out[4 * E + i1] = sw1;
        out[5 * E + i1] = mf1;
    }
}

extern "C" void kernel_launch(void* const* d_in, const int* in_sizes, int n_in,
                              void* d_out, int out_size)
{
    const float* coords = (const float*)d_in[0];
    const int*   esrc   = (const int*)  d_in[1];
    const int*   edst   = (const int*)  d_in[2];
    const float* shifts = (const float*)d_in[3];
    const float* cells  = (const float*)d_in[4];
    float*       out    = (float*)d_out;

    const int N = in_sizes[0] / 3;
    const int E = in_sizes[1];

    pad_coords_kernel<<<(N + 255) / 256, 256>>>(coords, N);

    const int blocks = (E + EPB - 1) / EPB;

    // PDL launch; fall back to a plain launch on error.
    cudaLaunchConfig_t cfg = {};
    cfg.gridDim  = dim3(blocks, 1, 1);
    cfg.blockDim = dim3(256, 1, 1);
    cfg.dynamicSmemBytes = 0;
    cfg.stream = 0;
    cudaLaunchAttribute attr[1];
    attr[0].id = cudaLaunchAttributeProgrammaticStreamSerialization;
    attr[0].val.programmaticStreamSerializationAllowed = 1;
    cfg.attrs = attr;
    cfg.numAttrs = 1;

    cudaError_t err = cudaLaunchKernelEx(&cfg, graph_edge_kernel,
                                         esrc, edst, shifts, cells, out, E);
    if (err != cudaSuccess) {
        (void)cudaGetLastError();
        graph_edge_kernel<<<blocks, 256>>>(esrc, edst, shifts, cells, out, E);
    }
}

// round 12
// speedup vs baseline: 1.0513x; 1.0513x over previous
#include <cuda_runtime.h>
#include <math_constants.h>

// Coords padded to float4 -> single LDG.128 per gather (16B aligned by definition).
__device__ float4 g_coords4[131072];

__global__ void __launch_bounds__(256) pad_coords_kernel(
    const float* __restrict__ coords, int n)
{
    int i = blockIdx.x * blockDim.x + threadIdx.x;
    if (i < n) {
        g_coords4[i] = make_float4(coords[3 * i + 0],
                                   coords[3 * i + 1],
                                   coords[3 * i + 2], 0.0f);
    }
    __threadfence();
    cudaTriggerProgrammaticLaunchCompletion();
}

#define EPB 512   // edges per chunk (2 per thread, 256 threads)

// Output layout (float32, out_size = 6*E):
//   [0 , 3E) : vec [E,3]   [3E,4E) : dist   [4E,5E) : switch   [5E,6E) : mask
// Persistent blocks; double-buffered stage -> ONE barrier per iteration.
__global__ void __launch_bounds__(256) graph_edge_kernel(
    const int*   __restrict__ esrc,
    const int*   __restrict__ edst,
    const float* __restrict__ shifts,
    const float* __restrict__ cells,
    float*       __restrict__ out,
    int E)
{
    __shared__ float stage[2][EPB * 3];

    const int t = threadIdx.x;
    const int nchunks = (E + EPB - 1) / EPB;
    const int stride  = gridDim.x;

    // cells: uniform broadcast loads, kept in registers for the whole kernel.
    const float c00 = __ldg(cells + 0), c01 = __ldg(cells + 1), c02 = __ldg(cells + 2);
    const float c10 = __ldg(cells + 3), c11 = __ldg(cells + 4), c12 = __ldg(cells + 5);
    const float c20 = __ldg(cells + 6), c21 = __ldg(cells + 7), c22 = __ldg(cells + 8);

    int chunk = blockIdx.x;

    // ---- prologue: streaming loads for first chunk (regs, deep MLP) ----
    int cs0 = 0, cd0 = 0, cs1 = 0, cd1 = 0;
    float cx0 = 0.f, cy0 = 0.f, cz0 = 0.f, cx1 = 0.f, cy1 = 0.f, cz1 = 0.f;
    if (chunk < nchunks) {
        const int i0 = chunk * EPB + t;
        const int i1 = i0 + 256;
        if (i0 < E) {
            cs0 = __ldg(esrc + i0);
            cd0 = __ldg(edst + i0);
            cx0 = __ldg(shifts + 3 * i0 + 0);
            cy0 = __ldg(shifts + 3 * i0 + 1);
            cz0 = __ldg(shifts + 3 * i0 + 2);
        }
        if (i1 < E) {
            cs1 = __ldg(esrc + i1);
            cd1 = __ldg(edst + i1);
            cx1 = __ldg(shifts + 3 * i1 + 0);
            cy1 = __ldg(shifts + 3 * i1 + 1);
            cz1 = __ldg(shifts + 3 * i1 + 2);
        }
    }

    // PDL: gathers read pad_coords_kernel's output — wait once, here.
    cudaGridDependencySynchronize();

    int buf = 0;
    while (chunk < nchunks) {
        const int base = chunk * EPB;
        const int i0 = base + t;
        const int i1 = i0 + 256;
        const bool a0 = (i0 < E);
        const bool a1 = (i1 < E);

        // ---- gathers for current chunk (idx already resident) ----
        float4 gs0 = make_float4(0.f,0.f,0.f,0.f), gd0 = gs0, gs1 = gs0, gd1 = gs0;
        if (a0) { gd0 = g_coords4[cd0]; gs0 = g_coords4[cs0]; }
        if (a1) { gd1 = g_coords4[cd1]; gs1 = g_coords4[cs1]; }

        // ---- prefetch next chunk's streaming loads (hide idx DRAM latency) ----
        const int next = chunk + stride;
        int ns0 = 0, nd0 = 0, ns1 = 0, nd1 = 0;
        float nx0 = 0.f, ny0 = 0.f, nz0 = 0.f, nx1 = 0.f, ny1 = 0.f, nz1 = 0.f;
        if (next < nchunks) {
            const int j0 = next * EPB + t;
            const int j1 = j0 + 256;
            if (j0 < E) {
                ns0 = __ldg(esrc + j0);
                nd0 = __ldg(edst + j0);
                nx0 = __ldg(shifts + 3 * j0 + 0);
                ny0 = __ldg(shifts + 3 * j0 + 1);
                nz0 = __ldg(shifts + 3 * j0 + 2);
            }
            if (j1 < E) {
                ns1 = __ldg(esrc + j1);
                nd1 = __ldg(edst + j1);
                nx1 = __ldg(shifts + 3 * j1 + 0);
                ny1 = __ldg(shifts + 3 * j1 + 1);
                nz1 = __ldg(shifts + 3 * j1 + 2);
            }
        }

        float dist0 = 0.f, sw0 = 0.f, mf0 = 0.f;
        float dist1 = 0.f, sw1 = 0.f, mf1 = 0.f;

        if (a0) {
            const float vx = (gd0.x - gs0.x) + cx0 * c00 + cy0 * c10 + cz0 * c20;
            const float vy = (gd0.y - gs0.y) + cx0 * c01 + cy0 * c11 + cz0 * c21;
            const float vz = (gd0.z - gs0.z) + cx0 * c02 + cy0 * c12 + cz0 * c22;
            stage[buf][3 * t + 0] = vx;
            stage[buf][3 * t + 1] = vy;
            stage[buf][3 * t + 2] = vz;
            dist0 = sqrtf(vx * vx + vy * vy + vz * vz);
            const bool m = dist0 < 5.0f;
            sw0 = m ? (0.5f * __cosf(dist0 * (CUDART_PI_F / 5.0f)) + 0.5f) : 0.0f;
            mf0 = m ? 1.0f : 0.0f;
        }
        if (a1) {
            const int u = t + 256;
            const float vx = (gd1.x - gs1.x) + cx1 * c00 + cy1 * c10 + cz1 * c20;
            const float vy = (gd1.y - gs1.y) + cx1 * c01 + cy1 * c11 + cz1 * c21;
            const float vz = (gd1.z - gs1.z) + cx1 * c02 + cy1 * c12 + cz1 * c22;
            stage[buf][3 * u + 0] = vx;
            stage[buf][3 * u + 1] = vy;
            stage[buf][3 * u + 2] = vz;
            dist1 = sqrtf(vx * vx + vy * vy + vz * vz);
            const bool m = dist1 < 5.0f;
            sw1 = m ? (0.5f * __cosf(dist1 * (CUDART_PI_F / 5.0f)) + 0.5f) : 0.0f;
            mf1 = m ? 1.0f : 0.0f;
        }

        // ONE barrier per iteration: makes stage[buf] writes visible AND
        // separates these stores from writes two iterations ahead (same buffer).
        __syncthreads();

        const int nf = min(EPB, E - base) * 3;
        #pragma unroll
        for (int k = t; k < EPB * 3; k += 256) {
            if (k < nf) out[base * 3 + k] = stage[buf][k];
        }

        if (a0) {
            out[3 * E + i0] = dist0;
            out[4 * E + i0] = sw0;
            out[5 * E + i0] = mf0;
        }
        if (a1) {
            out[3 * E + i1] = dist1;
            out[4 * E + i1] = sw1;
            out[5 * E + i1] = mf1;
        }

        // rotate pipeline registers / flip buffer
        cs0 = ns0; cd0 = nd0; cs1 = ns1; cd1 = nd1;
        cx0 = nx0; cy0 = ny0; cz0 = nz0;
        cx1 = nx1; cy1 = ny1; cz1 = nz1;
        buf ^= 1;
        chunk = next;
    }
}

extern "C" void kernel_launch(void* const* d_in, const int* in_sizes, int n_in,
                              void* d_out, int out_size)
{
    const float* coords = (const float*)d_in[0];
    const int*   esrc   = (const int*)  d_in[1];
    const int*   edst   = (const int*)  d_in[2];
    const float* shifts = (const float*)d_in[3];
    const float* cells  = (const float*)d_in[4];
    float*       out    = (float*)d_out;

    const int N = in_sizes[0] / 3;
    const int E = in_sizes[1];
    const int nchunks = (E + EPB - 1) / EPB;

    pad_coords_kernel<<<(N + 255) / 256, 256>>>(coords, N);

    // Exactly one resident wave of persistent blocks.
    int blocks = 592;  // fallback: 148 SMs * 4
    {
        int dev = 0, sms = 0, maxb = 0;
        if (cudaGetDevice(&dev) == cudaSuccess &&
            cudaDeviceGetAttribute(&sms, cudaDevAttrMultiProcessorCount, dev) == cudaSuccess &&
            cudaOccupancyMaxActiveBlocksPerMultiprocessor(&maxb, graph_edge_kernel, 256, 0) == cudaSuccess &&
            sms > 0 && maxb > 0) {
            blocks = sms * maxb;
        }
    }
    if (blocks > nchunks) blocks = nchunks;

    // PDL launch; fall back to a plain launch on error.
    cudaLaunchConfig_t cfg = {};
    cfg.gridDim  = dim3(blocks, 1, 1);
    cfg.blockDim = dim3(256, 1, 1);
    cfg.dynamicSmemBytes = 0;
    cfg.stream = 0;
    cudaLaunchAttribute attr[1];
    attr[0].id = cudaLaunchAttributeProgrammaticStreamSerialization;
    attr[0].val.programmaticStreamSerializationAllowed = 1;
    cfg.attrs = attr;
    cfg.numAttrs = 1;

    cudaError_t err = cudaLaunchKernelEx(&cfg, graph_edge_kernel,
                                         esrc, edst, shifts, cells, out, E);
    if (err != cudaSuccess) {
        (void)cudaGetLastError();
        graph_edge_kernel<<<blocks, 256>>>(esrc, edst, shifts, cells, out, E);
    }
}

// round 13
// speedup vs baseline: 1.0550x; 1.0035x over previous
#include <cuda_runtime.h>
#include <math_constants.h>

// Coords padded to float4 -> single LDG.128 per gather (16B aligned by definition).
__device__ float4 g_coords4[131072];

__global__ void __launch_bounds__(256) pad_coords_kernel(
    const float* __restrict__ coords, int n)
{
    int i = blockIdx.x * blockDim.x + threadIdx.x;
    if (i < n) {
        g_coords4[i] = make_float4(coords[3 * i + 0],
                                   coords[3 * i + 1],
                                   coords[3 * i + 2], 0.0f);
    }
    __threadfence();
    cudaTriggerProgrammaticLaunchCompletion();
}

#define NT  128               // threads per block (halved barrier scope vs R5)
#define EPB (NT * 2)          // 256 edges per block (2 per thread)

// Output layout (float32, out_size = 6*E):
//   [0 , 3E) : vec [E,3]   [3E,4E) : dist   [4E,5E) : switch   [5E,6E) : mask
__global__ void __launch_bounds__(NT) graph_edge_kernel(
    const int*   __restrict__ esrc,
    const int*   __restrict__ edst,
    const float* __restrict__ shifts,
    const float* __restrict__ cells,
    float*       __restrict__ out,
    int E)
{
    __shared__ float s_cells[9];
    __shared__ float stage[EPB * 3];   // vec staging -> contiguous STG

    const int t = threadIdx.x;
    const int base = blockIdx.x * EPB;
    const int i0 = base + t;
    const int i1 = i0 + NT;
    const bool a0 = (i0 < E);
    const bool a1 = (i1 < E);

    if (t < 9) s_cells[t] = __ldg(cells + t);

    // ---- issue ALL independent streaming loads up front (deep MLP) ----
    int s0 = 0, d0 = 0, s1 = 0, d1 = 0;
    float sx0 = 0.f, sy0 = 0.f, sz0 = 0.f, sx1 = 0.f, sy1 = 0.f, sz1 = 0.f;
    if (a0) {
        s0  = __ldg(esrc + i0);
        d0  = __ldg(edst + i0);
        sx0 = __ldg(shifts + 3 * i0 + 0);
        sy0 = __ldg(shifts + 3 * i0 + 1);
        sz0 = __ldg(shifts + 3 * i0 + 2);
    }
    if (a1) {
        s1  = __ldg(esrc + i1);
        d1  = __ldg(edst + i1);
        sx1 = __ldg(shifts + 3 * i1 + 0);
        sy1 = __ldg(shifts + 3 * i1 + 1);
        sz1 = __ldg(shifts + 3 * i1 + 2);
    }

    // s_cells visibility; cost hides under in-flight loads above.
    __syncthreads();

    // PDL: gathers read pad_coords_kernel's output — wait for it here.
    cudaGridDependencySynchronize();

    float4 cs0 = make_float4(0.f, 0.f, 0.f, 0.f), cd0 = cs0, cs1 = cs0, cd1 = cs0;
    if (a0) { cd0 = g_coords4[d0]; cs0 = g_coords4[s0]; }
    if (a1) { cd1 = g_coords4[d1]; cs1 = g_coords4[s1]; }

    const float c00 = s_cells[0], c01 = s_cells[1], c02 = s_cells[2];
    const float c10 = s_cells[3], c11 = s_cells[4], c12 = s_cells[5];
    const float c20 = s_cells[6], c21 = s_cells[7], c22 = s_cells[8];

    float dist0 = 0.f, sw0 = 0.f, mf0 = 0.f;
    float dist1 = 0.f, sw1 = 0.f, mf1 = 0.f;

    if (a0) {
        const float vx = (cd0.x - cs0.x) + sx0 * c00 + sy0 * c10 + sz0 * c20;
        const float vy = (cd0.y - cs0.y) + sx0 * c01 + sy0 * c11 + sz0 * c21;
        const float vz = (cd0.z - cs0.z) + sx0 * c02 + sy0 * c12 + sz0 * c22;
        stage[3 * t + 0] = vx;
        stage[3 * t + 1] = vy;
        stage[3 * t + 2] = vz;
        dist0 = sqrtf(vx * vx + vy * vy + vz * vz);
        const bool m = dist0 < 5.0f;
        sw0 = m ? (0.5f * __cosf(dist0 * (CUDART_PI_F / 5.0f)) + 0.5f) : 0.0f;
        mf0 = m ? 1.0f : 0.0f;
    }
    if (a1) {
        const int u = t + NT;
        const float vx = (cd1.x - cs1.x) + sx1 * c00 + sy1 * c10 + sz1 * c20;
        const float vy = (cd1.y - cs1.y) + sx1 * c01 + sy1 * c11 + sz1 * c21;
        const float vz = (cd1.z - cs1.z) + sx1 * c02 + sy1 * c12 + sz1 * c22;
        stage[3 * u + 0] = vx;
        stage[3 * u + 1] = vy;
        stage[3 * u + 2] = vz;
        dist1 = sqrtf(vx * vx + vy * vy + vz * vz);
        const bool m = dist1 < 5.0f;
        sw1 = m ? (0.5f * __cosf(dist1 * (CUDART_PI_F / 5.0f)) + 0.5f) : 0.0f;
        mf1 = m ? 1.0f : 0.0f;
    }

    __syncthreads();

    // ---- contiguous scalar stores of staged vec (1 wavefront / warp / instr) ----
    const int nf = (base < E) ? min(EPB, E - base) * 3 : 0;
    #pragma unroll
    for (int k = t; k < EPB * 3; k += NT) {
        if (k < nf) out[base * 3 + k] = stage[k];
    }

    if (a0) {
        out[3 * E + i0] = dist0;
        out[4 * E + i0] = sw0;
        out[5 * E + i0] = mf0;
    }
    if (a1) {
        out[3 * E + i1] = dist1;
        out[4 * E + i1] = sw1;
        out[5 * E + i1] = mf1;
    }
}

extern "C" void kernel_launch(void* const* d_in, const int* in_sizes, int n_in,
                              void* d_out, int out_size)
{
    const float* coords = (const float*)d_in[0];
    const int*   esrc   = (const int*)  d_in[1];
    const int*   edst   = (const int*)  d_in[2];
    const float* shifts = (const float*)d_in[3];
    const float* cells  = (const float*)d_in[4];
    float*       out    = (float*)d_out;

    const int N = in_sizes[0] / 3;
    const int E = in_sizes[1];

    pad_coords_kernel<<<(N + 255) / 256, 256>>>(coords, N);

    const int blocks = (E + EPB - 1) / EPB;

    // PDL launch; fall back to a plain launch on error.
    cudaLaunchConfig_t cfg = {};
    cfg.gridDim  = dim3(blocks, 1, 1);
    cfg.blockDim = dim3(NT, 1, 1);
    cfg.dynamicSmemBytes = 0;
    cfg.stream = 0;
    cudaLaunchAttribute attr[1];
    attr[0].id = cudaLaunchAttributeProgrammaticStreamSerialization;
    attr[0].val.programmaticStreamSerializationAllowed = 1;
    cfg.attrs = attr;
    cfg.numAttrs = 1;

    cudaError_t err = cudaLaunchKernelEx(&cfg, graph_edge_kernel,
                                         esrc, edst, shifts, cells, out, E);
    if (err != cudaSuccess) {
        (void)cudaGetLastError();
        graph_edge_kernel<<<blocks, NT>>>(esrc, edst, shifts, cells, out, E);
    }
}

// round 14
// speedup vs baseline: 1.0731x; 1.0172x over previous
#include <cuda_runtime.h>
#include <math_constants.h>

// Coords padded to float4 -> single LDG.128 per gather (16B aligned by definition).
__device__ float4 g_coords4[131072];

__global__ void __launch_bounds__(256) pad_coords_kernel(
    const float* __restrict__ coords, int n)
{
    int i = blockIdx.x * blockDim.x + threadIdx.x;
    if (i < n) {
        g_coords4[i] = make_float4(coords[3 * i + 0],
                                   coords[3 * i + 1],
                                   coords[3 * i + 2], 0.0f);
    }
    __threadfence();
    cudaTriggerProgrammaticLaunchCompletion();
}

#define EPB 512   // edges per block (2 per thread, 256 threads)

// Output layout (float32, out_size = 6*E):
//   [0 , 3E) : vec [E,3]   [3E,4E) : dist   [4E,5E) : switch   [5E,6E) : mask

// ---- full-block kernel: ZERO bounds checks (block fully in range) ----
__global__ void __launch_bounds__(256) graph_edge_full_kernel(
    const int*   __restrict__ esrc,
    const int*   __restrict__ edst,
    const float* __restrict__ shifts,
    const float* __restrict__ cells,
    float*       __restrict__ out,
    int E)
{
    __shared__ float s_cells[9];
    __shared__ float stage[EPB * 3];

    const int t = threadIdx.x;
    const int base = blockIdx.x * EPB;
    const int i0 = base + t;
    const int i1 = i0 + 256;

    if (t < 9) s_cells[t] = __ldg(cells + t);

    // all streaming loads unconditional, issued up front (deep MLP)
    const int   s0  = __ldg(esrc + i0);
    const int   d0  = __ldg(edst + i0);
    const int   s1  = __ldg(esrc + i1);
    const int   d1  = __ldg(edst + i1);
    const float sx0 = __ldg(shifts + 3 * i0 + 0);
    const float sy0 = __ldg(shifts + 3 * i0 + 1);
    const float sz0 = __ldg(shifts + 3 * i0 + 2);
    const float sx1 = __ldg(shifts + 3 * i1 + 0);
    const float sy1 = __ldg(shifts + 3 * i1 + 1);
    const float sz1 = __ldg(shifts + 3 * i1 + 2);

    __syncthreads();   // s_cells visibility; hides under in-flight loads

    // PDL: gathers read pad_coords_kernel's output — wait for it here.
    cudaGridDependencySynchronize();

    const float4 cd0 = g_coords4[d0];
    const float4 cs0 = g_coords4[s0];
    const float4 cd1 = g_coords4[d1];
    const float4 cs1 = g_coords4[s1];

    const float c00 = s_cells[0], c01 = s_cells[1], c02 = s_cells[2];
    const float c10 = s_cells[3], c11 = s_cells[4], c12 = s_cells[5];
    const float c20 = s_cells[6], c21 = s_cells[7], c22 = s_cells[8];

    const float vx0 = (cd0.x - cs0.x) + sx0 * c00 + sy0 * c10 + sz0 * c20;
    const float vy0 = (cd0.y - cs0.y) + sx0 * c01 + sy0 * c11 + sz0 * c21;
    const float vz0 = (cd0.z - cs0.z) + sx0 * c02 + sy0 * c12 + sz0 * c22;
    stage[3 * t + 0] = vx0;
    stage[3 * t + 1] = vy0;
    stage[3 * t + 2] = vz0;
    const float dist0 = sqrtf(vx0 * vx0 + vy0 * vy0 + vz0 * vz0);
    const bool  m0 = dist0 < 5.0f;
    const float sw0 = m0 ? (0.5f * __cosf(dist0 * (CUDART_PI_F / 5.0f)) + 0.5f) : 0.0f;
    const float mf0 = m0 ? 1.0f : 0.0f;

    const int u = t + 256;
    const float vx1 = (cd1.x - cs1.x) + sx1 * c00 + sy1 * c10 + sz1 * c20;
    const float vy1 = (cd1.y - cs1.y) + sx1 * c01 + sy1 * c11 + sz1 * c21;
    const float vz1 = (cd1.z - cs1.z) + sx1 * c02 + sy1 * c12 + sz1 * c22;
    stage[3 * u + 0] = vx1;
    stage[3 * u + 1] = vy1;
    stage[3 * u + 2] = vz1;
    const float dist1 = sqrtf(vx1 * vx1 + vy1 * vy1 + vz1 * vz1);
    const bool  m1 = dist1 < 5.0f;
    const float sw1 = m1 ? (0.5f * __cosf(dist1 * (CUDART_PI_F / 5.0f)) + 0.5f) : 0.0f;
    const float mf1 = m1 ? 1.0f : 0.0f;

    __syncthreads();

    // contiguous scalar stores of staged vec, no bounds checks
    float* vout = out + base * 3;
    #pragma unroll
    for (int j = 0; j < 6; j++) {
        vout[t + j * 256] = stage[t + j * 256];
    }

    out[3 * E + i0] = dist0;
    out[4 * E + i0] = sw0;
    out[5 * E + i0] = mf0;
    out[3 * E + i1] = dist1;
    out[4 * E + i1] = sw1;
    out[5 * E + i1] = mf1;
}

// ---- tail kernel: guarded, handles [tailStart, E) (launched only if needed) ----
__global__ void __launch_bounds__(256) graph_edge_tail_kernel(
    const int*   __restrict__ esrc,
    const int*   __restrict__ edst,
    const float* __restrict__ shifts,
    const float* __restrict__ cells,
    float*       __restrict__ out,
    int E, int tailStart)
{
    const int i = tailStart + blockIdx.x * blockDim.x + threadIdx.x;
    if (i >= E) return;

    cudaGridDependencySynchronize();

    const float c00 = __ldg(cells + 0), c01 = __ldg(cells + 1), c02 = __ldg(cells + 2);
    const float c10 = __ldg(cells + 3), c11 = __ldg(cells + 4), c12 = __ldg(cells + 5);
    const float c20 = __ldg(cells + 6), c21 = __ldg(cells + 7), c22 = __ldg(cells + 8);

    const int s = __ldg(esrc + i);
    const int d = __ldg(edst + i);
    const float4 cd = g_coords4[d];
    const float4 cs = g_coords4[s];
    const float sx = __ldg(shifts + 3 * i + 0);
    const float sy = __ldg(shifts + 3 * i + 1);
    const float sz = __ldg(shifts + 3 * i + 2);

    const float vx = (cd.x - cs.x) + sx * c00 + sy * c10 + sz * c20;
    const float vy = (cd.y - cs.y) + sx * c01 + sy * c11 + sz * c21;
    const float vz = (cd.z - cs.z) + sx * c02 + sy * c12 + sz * c22;
    out[3 * i + 0] = vx;
    out[3 * i + 1] = vy;
    out[3 * i + 2] = vz;
    const float dist = sqrtf(vx * vx + vy * vy + vz * vz);
    const bool m = dist < 5.0f;
    out[3 * E + i] = dist;
    out[4 * E + i] = m ? (0.5f * __cosf(dist * (CUDART_PI_F / 5.0f)) + 0.5f) : 0.0f;
    out[5 * E + i] = m ? 1.0f : 0.0f;
}

extern "C" void kernel_launch(void* const* d_in, const int* in_sizes, int n_in,
                              void* d_out, int out_size)
{
    const float* coords = (const float*)d_in[0];
    const int*   esrc   = (const int*)  d_in[1];
    const int*   edst   = (const int*)  d_in[2];
    const float* shifts = (const float*)d_in[3];
    const float* cells  = (const float*)d_in[4];
    float*       out    = (float*)d_out;

    const int N = in_sizes[0] / 3;
    const int E = in_sizes[1];
    const int fullBlocks = E / EPB;
    const int tailStart  = fullBlocks * EPB;

    pad_coords_kernel<<<(N + 255) / 256, 256>>>(coords, N);

    cudaLaunchAttribute attr[1];
    attr[0].id = cudaLaunchAttributeProgrammaticStreamSerialization;
    attr[0].val.programmaticStreamSerializationAllowed = 1;

    if (fullBlocks > 0) {
        cudaLaunchConfig_t cfg = {};
        cfg.gridDim  = dim3(fullBlocks, 1, 1);
        cfg.blockDim = dim3(256, 1, 1);
        cfg.dynamicSmemBytes = 0;
        cfg.stream = 0;
        cfg.attrs = attr;
        cfg.numAttrs = 1;
        cudaError_t err = cudaLaunchKernelEx(&cfg, graph_edge_full_kernel,
                                             esrc, edst, shifts, cells, out, E);
        if (err != cudaSuccess) {
            (void)cudaGetLastError();
            graph_edge_full_kernel<<<fullBlocks, 256>>>(esrc, edst, shifts, cells, out, E);
        }
    }
    if (tailStart < E) {
        const int nt = E - tailStart;
        graph_edge_tail_kernel<<<(nt + 255) / 256, 256>>>(
            esrc, edst, shifts, cells, out, E, tailStart);
    }
}